// round 8
// baseline (speedup 1.0000x reference)
#include <cuda_runtime.h>
#include <cuda_fp16.h>
#include <cstdint>

#define NEXP   8
#define DIM_S  64
#define HID    256
#define BM     128
#define NTHR   256

// Pre-shuffled fp16 B-fragment streams (built by convw each launch).
// Layout: [c][wn][ks][quarter q4=rg*2+nthalf][lane][j(=nt within half)] u32
//   u32 = {W[k][n], W[k+1][n]},  k = ks*16 + (lane&3)*2 + 8*rg,
//   n = wn*64 + nt*8 + (lane>>2),  nt = (q4&1)*4 + j
__device__ uint32_t g_w1s[NEXP * 4 * 4 * 512];    //  65536 u32 (256 KB)
__device__ uint32_t g_w2s[NEXP * 4 * 16 * 512];   // 262144 u32 (1 MB)

// ---- SMEM (bytes) ----
// A1: fp16 [128 r][64 k], 128 B/row, chunk swizzle: chunk ^= (row&7)
// H1: fp16 [128 r][256 k], 512 B/row, same swizzle (low 3 chunk bits)
// BIAS: per-group copy {b1[256], b2[256], w3[256]} f32
#define OFF_A1    0
#define OFF_H1    16384
#define OFF_BIAS  81920          // + wm*3072 : b1 @ +0, b2 @ +1024, w3 @ +2048
#define OFF_PART  88064          // [128 rows][4 wn] f32
#define SMEM_BYTES 90112

__device__ __forceinline__ uint32_t packh2(float lo, float hi) {
    __half2 h = __floats2half2_rn(lo, hi);
    return *reinterpret_cast<uint32_t*>(&h);
}
__device__ __forceinline__ uint32_t smem_u32(const void* p) {
    uint32_t a;
    asm("{ .reg .u64 t; cvta.to.shared.u64 t, %1; cvt.u32.u64 %0, t; }" : "=r"(a) : "l"(p));
    return a;
}
__device__ __forceinline__ void mma_f16(float c[4], const uint32_t* a,
                                        uint32_t b0, uint32_t b1) {
    asm volatile(
        "mma.sync.aligned.m16n8k16.row.col.f32.f16.f16.f32 "
        "{%0,%1,%2,%3}, {%4,%5,%6,%7}, {%8,%9}, {%0,%1,%2,%3};"
        : "+f"(c[0]), "+f"(c[1]), "+f"(c[2]), "+f"(c[3])
        : "r"(a[0]), "r"(a[1]), "r"(a[2]), "r"(a[3]), "r"(b0), "r"(b1));
}
__device__ __forceinline__ void ldmx4(uint32_t* a, uint32_t addr) {
    asm volatile("ldmatrix.sync.aligned.m8n8.x4.shared.b16 {%0,%1,%2,%3}, [%4];"
        : "=r"(a[0]), "=r"(a[1]), "=r"(a[2]), "=r"(a[3]) : "r"(addr));
}
__device__ __forceinline__ void gbar(int id) {
    asm volatile("bar.sync %0, 128;" :: "r"(id) : "memory");
}

// ---- prologue: build B-fragment streams from fp32 row-major weights ----
__global__ void __launch_bounds__(NTHR)
convw(const float* __restrict__ W1, const float* __restrict__ W2)
{
    int i = blockIdx.x * NTHR + threadIdx.x;
    if (i < NEXP * 4 * 4 * 512) {            // W1 stream
        int j = i & 3, lane = (i >> 2) & 31, q4 = (i >> 7) & 3;
        int ks = (i >> 9) & 3, w = (i >> 11) & 3, c = i >> 13;
        int rg = q4 >> 1, nt = (q4 & 1) * 4 + j;
        int n = w * 64 + nt * 8 + (lane >> 2);
        int k = ks * 16 + (lane & 3) * 2 + rg * 8;
        const float* p = W1 + ((size_t)c * DIM_S + k) * HID + n;
        g_w1s[i] = packh2(p[0], p[HID]);
    } else {
        i -= NEXP * 4 * 4 * 512;
        if (i < NEXP * 4 * 16 * 512) {       // W2 stream
            int j = i & 3, lane = (i >> 2) & 31, q4 = (i >> 7) & 3;
            int ks = (i >> 9) & 15, w = (i >> 13) & 3, c = i >> 15;
            int rg = q4 >> 1, nt = (q4 & 1) * 4 + j;
            int n = w * 64 + nt * 8 + (lane >> 2);
            int k = ks * 16 + (lane & 3) * 2 + rg * 8;
            const float* p = W2 + ((size_t)c * HID + k) * HID + n;
            g_w2s[i] = packh2(p[0], p[HID]);
        }
    }
}

// GEMM: acc[4][8][4] += A(rows wm*64..+63, K = TOT16*16, smem swizzled
// row-major fp16, ROWB bytes/row) * B(fragment stream, this warp's 64 cols).
template<int TOT16, int ROWB>
__device__ __forceinline__ void gemm(const uint32_t* __restrict__ bs,
                                     uint32_t afb, float acc[4][8][4],
                                     int lane, int wm64)
{
    const int arow = wm64 + ((lane >> 3) & 1) * 8 + (lane & 7);
    const int jj   = lane >> 4;
    const uint32_t abase = afb + arow * ROWB;
    const int      amask = arow & 7;

    uint32_t breg[2][16];   // [ring][nt*2+rg]
    uint32_t areg[2][4];

    auto loadB = [&](int ks, uint32_t* b) {
        const uint4* p = reinterpret_cast<const uint4*>(
            bs + (size_t)ks * 512 + lane * 4);
        uint4 v0 = __ldg(p);        // rg0, nt0-3
        uint4 v1 = __ldg(p + 32);   // rg0, nt4-7
        uint4 v2 = __ldg(p + 64);   // rg1, nt0-3
        uint4 v3 = __ldg(p + 96);   // rg1, nt4-7
        b[0]  = v0.x; b[2]  = v0.y; b[4]  = v0.z; b[6]  = v0.w;
        b[8]  = v1.x; b[10] = v1.y; b[12] = v1.z; b[14] = v1.w;
        b[1]  = v2.x; b[3]  = v2.y; b[5]  = v2.z; b[7]  = v2.w;
        b[9]  = v3.x; b[11] = v3.y; b[13] = v3.z; b[15] = v3.w;
    };
    auto loadA = [&](int ks, int mt, uint32_t* a) {
        int chunk = (2 * ks + jj) ^ amask;
        ldmx4(a, abase + mt * 16 * ROWB + chunk * 16);
    };

    loadB(0, breg[0]);
    loadA(0, 0, areg[0]);

    #pragma unroll
    for (int ks = 0; ks < TOT16; ks++) {
        if (ks + 1 < TOT16) loadB(ks + 1, breg[(ks + 1) & 1]);
        const uint32_t* b = breg[ks & 1];
        #pragma unroll
        for (int mt = 0; mt < 4; mt++) {
            if (!(mt == 3 && ks + 1 == TOT16))
                loadA(mt == 3 ? ks + 1 : ks, (mt + 1) & 3, areg[(mt + 1) & 1]);
            const uint32_t* a = areg[mt & 1];
            #pragma unroll
            for (int nt = 0; nt < 8; nt++)
                mma_f16(acc[mt][nt], a, b[nt * 2], b[nt * 2 + 1]);
        }
    }
}

__global__ void __launch_bounds__(NTHR, 1)
moe_disc_mma(const float* __restrict__ st,
             const float* __restrict__ b1, const float* __restrict__ b2,
             const float* __restrict__ W3, const float* __restrict__ b3,
             float* __restrict__ out)
{
    extern __shared__ char smem[];
    float* smf = reinterpret_cast<float*>(smem);
    const uint32_t sb = smem_u32(smem);
    const int tid  = threadIdx.x;
    const int wid  = tid >> 5;
    const int lane = tid & 31;
    const int wm   = wid >> 2;        // group: 0 = rows 0-63, 1 = rows 64-127
    const int wn   = wid & 3;         // 64-col block
    const int wm64 = wm * 64;
    const int lt   = tid & 127;       // thread index within group
    const int c    = blockIdx.y;
    const int m0   = blockIdx.x * BM;

    const int gB1 = (OFF_BIAS >> 2) + wm * 768;         // group bias base (f32)
    const int gB2 = gB1 + 256;
    const int gW3 = gB1 + 512;

    // ---- group-private staging: biases/w3 copy + own 64 A1 rows ----
    smf[gB1 + lt] = b1[c * HID + lt];  smf[gB1 + 128 + lt] = b1[c * HID + 128 + lt];
    smf[gB2 + lt] = b2[c * HID + lt];  smf[gB2 + 128 + lt] = b2[c * HID + 128 + lt];
    smf[gW3 + lt] = W3[c * HID + lt];  smf[gW3 + 128 + lt] = W3[c * HID + 128 + lt];

    #pragma unroll
    for (int i = 0; i < 8; i++) {
        int idx = lt + i * 128;         // 0..1023 float4 within group
        int row = wm64 + (idx >> 4), f4 = idx & 15;
        float4 v = *reinterpret_cast<const float4*>(
            st + (size_t)(m0 + row) * DIM_S + f4 * 4);
        uint32_t byte = OFF_A1 + row * 128
                      + (uint32_t)(((f4 >> 1) ^ (row & 7)) * 16 + 8 * (f4 & 1));
        *reinterpret_cast<uint2*>(smem + byte) =
            make_uint2(packh2(v.x, v.y), packh2(v.z, v.w));
    }
    gbar(wm + 1);

    float acc[4][8][4];
    #pragma unroll
    for (int a = 0; a < 4; a++)
        #pragma unroll
        for (int b = 0; b < 8; b++)
            #pragma unroll
            for (int e = 0; e < 4; e++) acc[a][b][e] = 0.f;

    // ---- layer 1 GEMM (K = 64) ----
    gemm<4, 128>(g_w1s + ((size_t)(c * 4 + wn)) * 2048, sb + OFF_A1,
                 acc, lane, wm64);

    // ---- epilogue 1: H1 = fp16(relu(acc + b1)), swizzled row-major ----
    {
        float b1v[16];
        #pragma unroll
        for (int nt = 0; nt < 8; nt++) {
            int k0 = wn * 64 + nt * 8 + 2 * (lane & 3);
            b1v[nt * 2]     = smf[gB1 + k0];
            b1v[nt * 2 + 1] = smf[gB1 + k0 + 1];
        }
        #pragma unroll
        for (int mt = 0; mt < 4; mt++)
            #pragma unroll
            for (int nt = 0; nt < 8; nt++) {
                int r0 = wm64 + mt * 16 + (lane >> 2);
                int chunk = wn * 8 + nt;
                uint32_t p0 = packh2(
                    fmaxf(acc[mt][nt][0] + b1v[nt * 2], 0.f),
                    fmaxf(acc[mt][nt][1] + b1v[nt * 2 + 1], 0.f));
                uint32_t p1 = packh2(
                    fmaxf(acc[mt][nt][2] + b1v[nt * 2], 0.f),
                    fmaxf(acc[mt][nt][3] + b1v[nt * 2 + 1], 0.f));
                uint32_t by0 = OFF_H1 + r0 * 512
                             + ((chunk ^ (r0 & 7)) * 16) + 4 * (lane & 3);
                int r1 = r0 + 8;
                uint32_t by1 = OFF_H1 + r1 * 512
                             + ((chunk ^ (r1 & 7)) * 16) + 4 * (lane & 3);
                *reinterpret_cast<uint32_t*>(smem + by0) = p0;
                *reinterpret_cast<uint32_t*>(smem + by1) = p1;
            }
    }
    #pragma unroll
    for (int a = 0; a < 4; a++)
        #pragma unroll
        for (int b = 0; b < 8; b++)
            #pragma unroll
            for (int e = 0; e < 4; e++) acc[a][b][e] = 0.f;

    gbar(wm + 1);   // group's H1 rows complete

    // ---- layer 2 GEMM (K = 256) ----
    gemm<16, 512>(g_w2s + ((size_t)(c * 4 + wn)) * 8192, sb + OFF_H1,
                  acc, lane, wm64);

    // ---- epilogue 2: d = relu(acc + b2) . w3, reduce, + b3 ----
    {
        float b2v[16], w3v[16];
        #pragma unroll
        for (int nt = 0; nt < 8; nt++) {
            int k0 = wn * 64 + nt * 8 + 2 * (lane & 3);
            b2v[nt * 2]     = smf[gB2 + k0];
            b2v[nt * 2 + 1] = smf[gB2 + k0 + 1];
            w3v[nt * 2]     = smf[gW3 + k0];
            w3v[nt * 2 + 1] = smf[gW3 + k0 + 1];
        }
        float p[4][2];
        #pragma unroll
        for (int mt = 0; mt < 4; mt++) { p[mt][0] = 0.f; p[mt][1] = 0.f; }
        #pragma unroll
        for (int mt = 0; mt < 4; mt++)
            #pragma unroll
            for (int nt = 0; nt < 8; nt++) {
                p[mt][0] += fmaxf(acc[mt][nt][0] + b2v[nt * 2], 0.f)     * w3v[nt * 2]
                          + fmaxf(acc[mt][nt][1] + b2v[nt * 2 + 1], 0.f) * w3v[nt * 2 + 1];
                p[mt][1] += fmaxf(acc[mt][nt][2] + b2v[nt * 2], 0.f)     * w3v[nt * 2]
                          + fmaxf(acc[mt][nt][3] + b2v[nt * 2 + 1], 0.f) * w3v[nt * 2 + 1];
            }
        #pragma unroll
        for (int off = 1; off <= 2; off <<= 1)
            #pragma unroll
            for (int mt = 0; mt < 4; mt++) {
                p[mt][0] += __shfl_xor_sync(0xFFFFFFFFu, p[mt][0], off);
                p[mt][1] += __shfl_xor_sync(0xFFFFFFFFu, p[mt][1], off);
            }
        if ((lane & 3) == 0) {
            #pragma unroll
            for (int mt = 0; mt < 4; mt++)
                #pragma unroll
                for (int h = 0; h < 2; h++) {
                    int row = wm64 + mt * 16 + (lane >> 2) + 8 * h;
                    smf[(OFF_PART >> 2) + row * 4 + wn] = p[mt][h];
                }
        }
    }
    gbar(wm + 1);   // group's partials complete
    if (lt < 64) {
        int row = wm64 + lt;
        const float* q = smf + (OFF_PART >> 2) + row * 4;
        out[(size_t)(m0 + row) * NEXP + c] = q[0] + q[1] + q[2] + q[3] + b3[c];
    }
}

extern "C" void kernel_launch(void* const* d_in, const int* in_sizes, int n_in,
                              void* d_out, int out_size)
{
    const float* st = (const float*)d_in[0];
    const float* W1 = (const float*)d_in[1];
    const float* b1 = (const float*)d_in[2];
    const float* W2 = (const float*)d_in[3];
    const float* b2 = (const float*)d_in[4];
    const float* W3 = (const float*)d_in[5];
    const float* b3 = (const float*)d_in[6];
    float* out = (float*)d_out;

    const int total = NEXP * 4 * 4 * 512 + NEXP * 4 * 16 * 512;  // 327680
    convw<<<(total + NTHR - 1) / NTHR, NTHR>>>(W1, W2);

    cudaFuncSetAttribute(moe_disc_mma,
                         cudaFuncAttributeMaxDynamicSharedMemorySize, SMEM_BYTES);
    dim3 grid(65536 / BM, NEXP);
    moe_disc_mma<<<grid, NTHR, SMEM_BYTES>>>(st, b1, b2, W3, b3, out);
}